// round 6
// baseline (speedup 1.0000x reference)
#include <cuda_runtime.h>
#include <cstdint>

// ImprovedVectorizationLoss: fused masked-L1 + BCE + continuity + recon-MSE.
// Uniform grid: every block stages one 256-record tile (cp.async) and, while
// that is in flight, computes its slice of the recon MSE. Ballot-based
// continuity; global atomics + last-block ticket finalize & self-reset.

#define M_ROW 4096
#define TPB   256
#define SEGS  16
#define SEG   (M_ROW / SEGS)         // 256 == TPB
#define NF4T  (SEG * 9 / 4)          // 576 float4 per tensor per block
#define BMAX  512
#define EPSV  1e-7f

__device__ float        g_acc[6];                  // [coord,width,bce,nvalid,cont,recon]
__device__ unsigned int g_ticket;
__device__ int          g_first_idx[BMAX * SEGS];
__device__ float2       g_first_p45[BMAX * SEGS];
__device__ float2       g_last_p45[BMAX * SEGS];

__device__ __forceinline__ float warpReduceSumF(float v) {
#pragma unroll
    for (int o = 16; o > 0; o >>= 1) v += __shfl_down_sync(0xffffffffu, v, o);
    return v;
}

__device__ __forceinline__ void cp16(void* s, const void* g) {
    unsigned saddr = (unsigned)__cvta_generic_to_shared(s);
    asm volatile("cp.async.cg.shared.global [%0], [%1], 16;" :: "r"(saddr), "l"(g));
}
#define CP_COMMIT() asm volatile("cp.async.commit_group;")
#define CP_WAIT0()  asm volatile("cp.async.wait_group 0;")

__global__ __launch_bounds__(TPB, 7) void loss_fused_kernel(
    const float* __restrict__ preds, const float* __restrict__ tgts,
    const float* __restrict__ rec,   const float* __restrict__ img,
    float* __restrict__ out, int B, int nrec, int nblocks)
{
    __shared__ float  sp[SEG * 9];    // 9 KB
    __shared__ float  st[SEG * 9];    // 9 KB
    __shared__ float2 s45[SEG];       // 2 KB
    __shared__ int    sfv[8];         // per-warp first-valid index (or SEG)
    __shared__ float  swred[6][8];
    __shared__ bool   s_is_last;

    const int tid  = threadIdx.x;
    const int bid  = blockIdx.x;
    const int lane = tid & 31;
    const int wid  = tid >> 5;

    float coordS = 0.f, widthS = 0.f, bceS = 0.f, nvS = 0.f, contS = 0.f, reconS = 0.f;

    // ---- 1) kick off cp.async staging of this block's 256-record tile ----
    {
        const size_t segbase = (size_t)bid * SEG * 9;
        const float4* p4 = reinterpret_cast<const float4*>(preds + segbase);
        const float4* t4 = reinterpret_cast<const float4*>(tgts  + segbase);
        float4* spd = reinterpret_cast<float4*>(sp);
        float4* std_ = reinterpret_cast<float4*>(st);
        for (int i = tid; i < NF4T; i += TPB) {
            cp16(&spd[i], &p4[i]);
            cp16(&std_[i], &t4[i]);
        }
        CP_COMMIT();
    }

    // ---- 2) recon MSE slice overlaps the cp.async fill ----
    {
        const float4* r4 = reinterpret_cast<const float4*>(rec);
        const float4* i4 = reinterpret_cast<const float4*>(img);
        const int n4 = nrec >> 2;
        for (int i = bid * TPB + tid; i < n4; i += nblocks * TPB) {
            float4 r = r4[i], m = i4[i];
            float dx = r.x - m.x, dy = r.y - m.y, dz = r.z - m.z, dw = r.w - m.w;
            reconS += dx * dx + dy * dy + dz * dz + dw * dw;
        }
    }

    // ---- 3) per-record losses (one record per thread) ----
    CP_WAIT0();
    __syncthreads();

    float p45x, p45y;
    unsigned vbit;
    {
        const float* pr = &sp[tid * 9];
        const float* tr = &st[tid * 9];
        float t8   = tr[8];
        float mask = (t8 > 0.5f) ? 1.0f : 0.0f;
        vbit = (t8 > 0.5f) ? 1u : 0u;

        float p4v = pr[4], p5v = pr[5];
        coordS += (fabsf(pr[0] - tr[0]) + fabsf(pr[1] - tr[1]) + fabsf(pr[2] - tr[2])
                 + fabsf(pr[3] - tr[3]) + fabsf(p4v - tr[4]) + fabsf(p5v - tr[5])) * mask;
        widthS += (fabsf(pr[6] - tr[6]) + fabsf(pr[7] - tr[7])) * mask;

        float p = fminf(fmaxf(pr[8], EPSV), 1.0f - EPSV);
        bceS   += -(t8 * __logf(p) + (1.0f - t8) * __logf(1.0f - p));
        nvS    += mask;

        p45x = p4v; p45y = p5v;
        s45[tid] = make_float2(p4v, p5v);
    }

    // ---- 4) continuity: registers + ballots ----
    unsigned b = __ballot_sync(0xffffffffu, vbit != 0);
    if (lane == 0) sfv[wid] = b ? (wid * 32 + __ffs(b) - 1) : SEG;
    __syncthreads();

    int nxt_cross = SEG;
#pragma unroll
    for (int w2 = 7; w2 >= 0; w2--)
        if (w2 > wid) nxt_cross = min(nxt_cross, sfv[w2]);

    const int rs = bid;
    if (vbit) {
        unsigned rem = (lane < 31) ? (b & (0xFFFFFFFFu << (lane + 1))) : 0u;
        int nxt = rem ? (wid * 32 + __ffs(rem) - 1) : nxt_cross;
        if (nxt < SEG) {
            float2 nb = s45[nxt];
            contS += 0.5f * (fabsf(p45x - nb.x) + fabsf(p45y - nb.y));
        } else {
            g_last_p45[rs] = make_float2(p45x, p45y);   // unique last valid
        }
    }
    if (tid == 0) {
        int f = SEG;
#pragma unroll
        for (int w2 = 0; w2 < 8; w2++) f = min(f, sfv[w2]);
        g_first_idx[rs] = f;
        if (f < SEG) g_first_p45[rs] = s45[f];
    }

    // ---- 5) block reduce + global atomics ----
    float vals[6] = {coordS, widthS, bceS, nvS, contS, reconS};
#pragma unroll
    for (int q = 0; q < 6; q++) {
        float v = warpReduceSumF(vals[q]);
        if (lane == 0) swred[q][wid] = v;
    }
    __syncthreads();
    if (wid == 0 && lane < 6) {
        float v = 0.f;
#pragma unroll
        for (int j = 0; j < 8; j++) v += swred[lane][j];
        atomicAdd(&g_acc[lane], v);
    }
    __syncthreads();

    // ---- 6) last-block finalize ----
    if (tid == 0) {
        __threadfence();   // release (cumulative: publishes whole block's writes)
        unsigned int t = atomicAdd(&g_ticket, 1u);
        s_is_last = (t == (unsigned int)(nblocks - 1));
    }
    __syncthreads();
    if (!s_is_last) return;
    __threadfence();       // acquire (single block)

    // cross-segment continuity fixup: one row per thread, prefetched loads
    float fix = 0.f;
    for (int r = tid; r < B; r += TPB) {
        int    fidx[SEGS];
        float2 fp[SEGS], lp[SEGS];
#pragma unroll
        for (int s = 0; s < SEGS; s++) {
            int q = r * SEGS + s;
            fidx[s] = g_first_idx[q];
            fp[s]   = g_first_p45[q];
            lp[s]   = g_last_p45[q];
        }
        float2 nf = make_float2(0.f, 0.f);
        bool have = false;
#pragma unroll
        for (int s = SEGS - 1; s >= 0; s--) {
            if (fidx[s] < SEG) {
                if (have) fix += 0.5f * (fabsf(lp[s].x - nf.x) + fabsf(lp[s].y - nf.y));
                nf = fp[s];
                have = true;
            }
        }
    }
    {
        float v = warpReduceSumF(fix);
        if (lane == 0) swred[0][wid] = v;
    }
    __syncthreads();
    if (tid == 0) {
        float fsum = 0.f;
#pragma unroll
        for (int j = 0; j < 8; j++) fsum += swred[0][j];

        double t0 = (double)g_acc[0], t1 = (double)g_acc[1], t2 = (double)g_acc[2];
        double nv = (double)g_acc[3];
        double t4 = (double)g_acc[4] + (double)fsum;
        double t5 = (double)g_acc[5];

        double coord    = (nv > 0.0) ? t0 / fmax(nv * 6.0, 1.0) : 0.0;
        double width    = (nv > 0.0) ? t1 / fmax(nv * 2.0, 1.0) : 0.0;
        double validity = t2 / ((double)B * (double)M_ROW);
        double cont     = t4 / (double)B;
        double recon    = t5 / (double)nrec;
        out[0] = (float)(coord + width + 2.0 * validity + 0.2 * cont + 0.1 * recon);

        g_ticket = 0u;
#pragma unroll
        for (int q = 0; q < 6; q++) g_acc[q] = 0.f;
        __threadfence();
    }
}

extern "C" void kernel_launch(void* const* d_in, const int* in_sizes, int n_in,
                              void* d_out, int out_size)
{
    const float* preds = (const float*)d_in[0];
    const float* tgts  = (const float*)d_in[1];
    const float* rec   = (const float*)d_in[2];
    const float* img   = (const float*)d_in[3];

    const int B    = in_sizes[0] / (M_ROW * 9);
    const int nrec = in_sizes[2];
    const int nblocks = B * SEGS;   // 4096 for reference shapes

    loss_fused_kernel<<<nblocks, TPB>>>(preds, tgts, rec, img,
                                        (float*)d_out, B, nrec, nblocks);
}

// round 7
// speedup vs baseline: 1.0636x; 1.0636x over previous
#include <cuda_runtime.h>
#include <cstdint>

// ImprovedVectorizationLoss: fused masked-L1 + BCE + continuity + recon-MSE.
// R5 geometry (2048 seg blocks x 512 records + 1024 recon blocks), smem cut
// to ~37KB (s45 aliased over sp tile0, ballot-based continuity) for 6
// blocks/SM. Atomics + last-block ticket finalize & self-reset.

#define M_ROW 4096
#define TPB   256
#define SEGS  8
#define SEG   512
#define NF4TILE 576              // float4 per tensor per 256-record tile
#define RECON_BLOCKS 1024
#define BMAX  512
#define EPSV  1e-7f

// Shared layout (static, 37.3 KB):
#define SP_OFF   0               // 2 tiles x 2304 floats = 18432 B
#define ST_OFF   18432           // 18432 B
#define MASK_OFF 36864           // 16 x u32 = 64 B
#define WRED_OFF 36928           // 6 x 8 floats = 192 B
#define LAST_OFF 37120           // 4 B
#define SMEM_BYTES 37124
// s45 (512 x float2 = 4 KB) aliases SP_OFF after record reads complete.

__device__ float        g_acc[6];   // [coord,width,bce,nvalid,cont,recon]
__device__ unsigned int g_ticket;
__device__ int          g_first_idx[BMAX * SEGS];
__device__ float2       g_first_p45[BMAX * SEGS];
__device__ float2       g_last_p45[BMAX * SEGS];

__device__ __forceinline__ float warpReduceSumF(float v) {
#pragma unroll
    for (int o = 16; o > 0; o >>= 1) v += __shfl_down_sync(0xffffffffu, v, o);
    return v;
}

__device__ __forceinline__ void cp16(void* s, const void* g) {
    unsigned saddr = (unsigned)__cvta_generic_to_shared(s);
    asm volatile("cp.async.cg.shared.global [%0], [%1], 16;" :: "r"(saddr), "l"(g));
}
#define CP_COMMIT() asm volatile("cp.async.commit_group;")
#define CP_WAIT(n)  asm volatile("cp.async.wait_group %0;" :: "n"(n))

__global__ __launch_bounds__(TPB, 6) void loss_fused_kernel(
    const float* __restrict__ preds, const float* __restrict__ tgts,
    const float* __restrict__ rec,   const float* __restrict__ img,
    float* __restrict__ out, int B, int nrec, int nblocks)
{
    __shared__ char smraw[SMEM_BYTES];
    float*    sp    = reinterpret_cast<float*>(smraw + SP_OFF);
    float*    st    = reinterpret_cast<float*>(smraw + ST_OFF);
    unsigned* smask = reinterpret_cast<unsigned*>(smraw + MASK_OFF);
    float*    swred = reinterpret_cast<float*>(smraw + WRED_OFF);   // [6][8]
    int*      slast = reinterpret_cast<int*>(smraw + LAST_OFF);
    float2*   s45   = reinterpret_cast<float2*>(smraw + SP_OFF);    // alias!

    const int tid  = threadIdx.x;
    const int bid  = blockIdx.x;
    const int lane = tid & 31;
    const int wid  = tid >> 5;
    const int nseg_blocks = B * SEGS;

    float coordS = 0.f, widthS = 0.f, bceS = 0.f, nvS = 0.f, contS = 0.f, reconS = 0.f;

    if (bid < nseg_blocks) {
        const size_t segbase = (size_t)bid * SEG * 9;
        const float4* p4 = reinterpret_cast<const float4*>(preds + segbase);
        const float4* t4 = reinterpret_cast<const float4*>(tgts  + segbase);

        // ---- stage tile0, tile1 via cp.async (separate groups) ----
#pragma unroll
        for (int tl = 0; tl < 2; tl++) {
            float4* spd = reinterpret_cast<float4*>(sp) + tl * NF4TILE;
            float4* std_ = reinterpret_cast<float4*>(st) + tl * NF4TILE;
            for (int i = tid; i < NF4TILE; i += TPB) {
                cp16(&spd[i], &p4[tl * NF4TILE + i]);
                cp16(&std_[i], &t4[tl * NF4TILE + i]);
            }
            CP_COMMIT();
        }

        // ---- process records: thread owns record tid (tile0) and 256+tid ----
        unsigned v[2];
        float2   q45[2];
#pragma unroll
        for (int tile = 0; tile < 2; tile++) {
            if (tile == 0) { CP_WAIT(1); } else { CP_WAIT(0); }
            __syncthreads();

            const float* pr = sp + (tile * 256 + tid) * 9;
            const float* tr = st + (tile * 256 + tid) * 9;
            float t8   = tr[8];
            float mask = (t8 > 0.5f) ? 1.0f : 0.0f;
            v[tile]    = (t8 > 0.5f) ? 1u : 0u;

            float a4 = pr[4], a5 = pr[5];
            coordS += (fabsf(pr[0] - tr[0]) + fabsf(pr[1] - tr[1]) + fabsf(pr[2] - tr[2])
                     + fabsf(pr[3] - tr[3]) + fabsf(a4 - tr[4]) + fabsf(a5 - tr[5])) * mask;
            widthS += (fabsf(pr[6] - tr[6]) + fabsf(pr[7] - tr[7])) * mask;

            float p = fminf(fmaxf(pr[8], EPSV), 1.0f - EPSV);
            bceS   += -(t8 * __logf(p) + (1.0f - t8) * __logf(1.0f - p));
            nvS    += mask;

            q45[tile] = make_float2(a4, a5);
        }
        __syncthreads();   // all sp/st reads done -> safe to alias s45 over sp

        // ---- publish p45 + validity masks ----
        s45[tid]       = q45[0];
        s45[256 + tid] = q45[1];
        unsigned b0 = __ballot_sync(0xffffffffu, v[0] != 0);
        unsigned b1 = __ballot_sync(0xffffffffu, v[1] != 0);
        if (lane == 0) { smask[wid] = b0; smask[8 + wid] = b1; }
        __syncthreads();

        // ---- continuity: next-valid via mask-word scan ----
        const int rs = bid;
#pragma unroll
        for (int tile = 0; tile < 2; tile++) {
            if (v[tile]) {
                const int j = tile * 256 + tid;        // record index
                const int k = j >> 5;                  // mask word (== tile*8+wid)
                unsigned rem = (lane < 31) ? (smask[k] & (0xFFFFFFFFu << (lane + 1))) : 0u;
                int k2 = k;
                while (rem == 0u && ++k2 < 16) rem = smask[k2];
                if (rem != 0u) {
                    int nxt = (k2 << 5) + __ffs(rem) - 1;
                    float2 nb = s45[nxt];
                    contS += 0.5f * (fabsf(q45[tile].x - nb.x) + fabsf(q45[tile].y - nb.y));
                } else {
                    g_last_p45[rs] = q45[tile];        // unique last valid
                }
            }
        }
        if (tid == 0) {
            int f = SEG;
#pragma unroll
            for (int k = 15; k >= 0; k--)
                if (smask[k]) f = (k << 5) + __ffs(smask[k]) - 1;
            g_first_idx[rs] = f;
            if (f < SEG) g_first_p45[rs] = s45[f];
        }
    } else {
        const int rb = bid - nseg_blocks;
        const float4* r4 = reinterpret_cast<const float4*>(rec);
        const float4* i4 = reinterpret_cast<const float4*>(img);
        const int n4 = nrec >> 2;
        for (int i = rb * TPB + tid; i < n4; i += RECON_BLOCKS * TPB) {
            float4 r = r4[i], m = i4[i];
            float dx = r.x - m.x, dy = r.y - m.y, dz = r.z - m.z, dw = r.w - m.w;
            reconS += dx * dx + dy * dy + dz * dz + dw * dw;
        }
    }

    // ---- block reduce + global atomic accumulate ----
    float vals[6] = {coordS, widthS, bceS, nvS, contS, reconS};
#pragma unroll
    for (int q = 0; q < 6; q++) {
        float vv = warpReduceSumF(vals[q]);
        if (lane == 0) swred[q * 8 + wid] = vv;
    }
    __syncthreads();
    if (wid == 0 && lane < 6) {
        float vv = 0.f;
#pragma unroll
        for (int j = 0; j < 8; j++) vv += swred[lane * 8 + j];
        atomicAdd(&g_acc[lane], vv);
    }
    __syncthreads();

    // ---- last-block finalize ----
    if (tid == 0) {
        __threadfence();   // release (cumulative: publishes whole block's writes)
        unsigned int t = atomicAdd(&g_ticket, 1u);
        slast[0] = (t == (unsigned int)(nblocks - 1)) ? 1 : 0;
    }
    __syncthreads();
    if (!slast[0]) return;
    __threadfence();       // acquire (single block)

    // cross-segment continuity fixup: one row per thread, prefetched loads
    float fix = 0.f;
    for (int r = tid; r < B; r += TPB) {
        int    fidx[SEGS];
        float2 fp[SEGS], lp[SEGS];
#pragma unroll
        for (int s = 0; s < SEGS; s++) {
            int q = r * SEGS + s;
            fidx[s] = g_first_idx[q];
            fp[s]   = g_first_p45[q];
            lp[s]   = g_last_p45[q];
        }
        float2 nf = make_float2(0.f, 0.f);
        bool have = false;
#pragma unroll
        for (int s = SEGS - 1; s >= 0; s--) {
            if (fidx[s] < SEG) {
                if (have) fix += 0.5f * (fabsf(lp[s].x - nf.x) + fabsf(lp[s].y - nf.y));
                nf = fp[s];
                have = true;
            }
        }
    }
    {
        float vv = warpReduceSumF(fix);
        if (lane == 0) swred[wid] = vv;
    }
    __syncthreads();
    if (tid == 0) {
        float fsum = 0.f;
#pragma unroll
        for (int j = 0; j < 8; j++) fsum += swred[j];

        double t0 = (double)g_acc[0], t1 = (double)g_acc[1], t2 = (double)g_acc[2];
        double nv = (double)g_acc[3];
        double t4 = (double)g_acc[4] + (double)fsum;
        double t5 = (double)g_acc[5];

        double coord    = (nv > 0.0) ? t0 / fmax(nv * 6.0, 1.0) : 0.0;
        double width    = (nv > 0.0) ? t1 / fmax(nv * 2.0, 1.0) : 0.0;
        double validity = t2 / ((double)B * (double)M_ROW);
        double cont     = t4 / (double)B;
        double recon    = t5 / (double)nrec;
        out[0] = (float)(coord + width + 2.0 * validity + 0.2 * cont + 0.1 * recon);

        g_ticket = 0u;
#pragma unroll
        for (int q = 0; q < 6; q++) g_acc[q] = 0.f;
        __threadfence();
    }
}

extern "C" void kernel_launch(void* const* d_in, const int* in_sizes, int n_in,
                              void* d_out, int out_size)
{
    const float* preds = (const float*)d_in[0];
    const float* tgts  = (const float*)d_in[1];
    const float* rec   = (const float*)d_in[2];
    const float* img   = (const float*)d_in[3];

    const int B    = in_sizes[0] / (M_ROW * 9);
    const int nrec = in_sizes[2];
    const int nblocks = B * SEGS + RECON_BLOCKS;   // 3072

    loss_fused_kernel<<<nblocks, TPB>>>(preds, tgts, rec, img,
                                        (float*)d_out, B, nrec, nblocks);
}

// round 8
// speedup vs baseline: 1.2667x; 1.1910x over previous
#include <cuda_runtime.h>
#include <cstdint>

// ImprovedVectorizationLoss: fused masked-L1 + BCE + continuity + recon-MSE.
// R5 structure with recon MSE folded into every segment block: the recon
// float4 stream executes while the block's cp.async tile copies are in
// flight, keeping DRAM busy through the staging latency. Uniform 2048-block
// grid; global atomics + last-block ticket finalize & self-reset.

#define M_ROW 4096
#define TPB   256
#define SEGS  8
#define SEG   (M_ROW / SEGS)         // 512
#define TILE  256
#define NTILE (SEG / TILE)           // 2
#define NF4T  (TILE * 9 / 4)         // 576 float4 per tile per tensor
#define BMAX  512
#define EPSV  1e-7f

__device__ float        g_acc[6];                  // [coord,width,bce,nvalid,cont,recon]
__device__ unsigned int g_ticket;
__device__ int          g_first_idx[BMAX * SEGS];
__device__ float2       g_first_p45[BMAX * SEGS];
__device__ float2       g_last_p45[BMAX * SEGS];

__device__ __forceinline__ float warpReduceSumF(float v) {
#pragma unroll
    for (int o = 16; o > 0; o >>= 1) v += __shfl_down_sync(0xffffffffu, v, o);
    return v;
}

__device__ __forceinline__ void cp16(void* s, const void* g) {
    unsigned saddr = (unsigned)__cvta_generic_to_shared(s);
    asm volatile("cp.async.cg.shared.global [%0], [%1], 16;" :: "r"(saddr), "l"(g));
}
#define CP_COMMIT() asm volatile("cp.async.commit_group;")
#define CP_WAIT(n)  asm volatile("cp.async.wait_group %0;" :: "n"(n))

// Spread bits of x to even bit positions of a 64-bit word.
__device__ __forceinline__ uint64_t bitspread(uint32_t a) {
    uint64_t x = a;
    x = (x | (x << 16)) & 0x0000FFFF0000FFFFull;
    x = (x | (x << 8))  & 0x00FF00FF00FF00FFull;
    x = (x | (x << 4))  & 0x0F0F0F0F0F0F0F0Full;
    x = (x | (x << 2))  & 0x3333333333333333ull;
    x = (x | (x << 1))  & 0x5555555555555555ull;
    return x;
}

__global__ __launch_bounds__(TPB) void loss_fused_kernel(
    const float* __restrict__ preds, const float* __restrict__ tgts,
    const float* __restrict__ rec,   const float* __restrict__ img,
    float* __restrict__ out, int B, int nrec, int nblocks)
{
    __shared__ float  sp[NTILE][TILE * 9];   // 18 KB
    __shared__ float  st[NTILE][TILE * 9];   // 18 KB
    __shared__ float2 s45[SEG];              // 4 KB
    __shared__ unsigned char smk[SEG];
    __shared__ int    sfv[8];                // per-warp first-valid (global-in-seg idx)
    __shared__ float  swred[6][8];
    __shared__ bool   s_is_last;

    const int tid  = threadIdx.x;
    const int bid  = blockIdx.x;
    const int lane = tid & 31;
    const int wid  = tid >> 5;

    float coordS = 0.f, widthS = 0.f, bceS = 0.f, nvS = 0.f, contS = 0.f, reconS = 0.f;

    const size_t segbase = (size_t)bid * SEG * 9;
    const float4* p4 = reinterpret_cast<const float4*>(preds + segbase);
    const float4* t4 = reinterpret_cast<const float4*>(tgts  + segbase);

    // ---- 1) stage tile0 then tile1 via cp.async, separate commit groups ----
#pragma unroll
    for (int tl = 0; tl < NTILE; tl++) {
        float4* spd = reinterpret_cast<float4*>(&sp[tl][0]);
        float4* std_ = reinterpret_cast<float4*>(&st[tl][0]);
        for (int i = tid; i < NF4T; i += TPB) {
            cp16(&spd[i], &p4[tl * NF4T + i]);
            cp16(&std_[i], &t4[tl * NF4T + i]);
        }
        CP_COMMIT();
    }

    // ---- 2) recon MSE slice overlaps the cp.async fill ----
    {
        const float4* r4 = reinterpret_cast<const float4*>(rec);
        const float4* i4 = reinterpret_cast<const float4*>(img);
        const int n4 = nrec >> 2;
        for (int i = bid * TPB + tid; i < n4; i += nblocks * TPB) {
            float4 r = r4[i], m = i4[i];
            float dx = r.x - m.x, dy = r.y - m.y, dz = r.z - m.z, dw = r.w - m.w;
            reconS += dx * dx + dy * dy + dz * dz + dw * dw;
        }
    }

    // ---- 3) process tiles; tile1 copy overlaps tile0 compute ----
#pragma unroll
    for (int tile = 0; tile < NTILE; tile++) {
        if (tile == 0) CP_WAIT(1); else CP_WAIT(0);
        __syncthreads();

        const float* pr = &sp[tile][tid * 9];
        const float* tr = &st[tile][tid * 9];
        float t8   = tr[8];
        float mask = (t8 > 0.5f) ? 1.0f : 0.0f;

        coordS += (fabsf(pr[0] - tr[0]) + fabsf(pr[1] - tr[1]) + fabsf(pr[2] - tr[2])
                 + fabsf(pr[3] - tr[3]) + fabsf(pr[4] - tr[4]) + fabsf(pr[5] - tr[5])) * mask;
        widthS += (fabsf(pr[6] - tr[6]) + fabsf(pr[7] - tr[7])) * mask;

        float p = fminf(fmaxf(pr[8], EPSV), 1.0f - EPSV);
        bceS   += -(t8 * __logf(p) + (1.0f - t8) * __logf(1.0f - p));
        nvS    += mask;

        int jseg = tile * TILE + tid;
        s45[jseg] = make_float2(pr[4], pr[5]);
        smk[jseg] = (unsigned char)(t8 > 0.5f ? 1 : 0);
    }
    __syncthreads();

    // ---- 4) continuity: ballot masks, ffs next-valid ----
    // Warp w owns entries [64w, 64w+64); thread lane l owns 64w+2l, 64w+2l+1.
    const int base = wid * 64;
    unsigned v0 = smk[base + 2 * lane];
    unsigned v1 = smk[base + 2 * lane + 1];
    unsigned b0 = __ballot_sync(0xffffffffu, v0 != 0);
    unsigned b1 = __ballot_sync(0xffffffffu, v1 != 0);
    uint64_t m64 = bitspread(b0) | (bitspread(b1) << 1);

    {
        int fvloc = m64 ? (__ffsll((long long)m64) - 1) : 64;
        if (lane == 0) sfv[wid] = (fvloc < 64) ? (base + fvloc) : SEG;
    }
    __syncthreads();

    int nxt_cross = SEG;
#pragma unroll
    for (int w2 = 7; w2 >= 0; w2--) {
        if (w2 > wid) nxt_cross = min(nxt_cross, sfv[w2]);
    }

    const int rs = bid;
#pragma unroll
    for (int jj = 0; jj < 2; jj++) {
        int pbit = 2 * lane + jj;
        unsigned valid = (jj == 0) ? v0 : v1;
        if (valid) {
            int j = base + pbit;
            int nxt;
            if (pbit < 63) {
                uint64_t rem = m64 & (~0ull << (pbit + 1));
                nxt = rem ? (base + __ffsll((long long)rem) - 1) : nxt_cross;
            } else {
                nxt = nxt_cross;
            }
            if (nxt < SEG) {
                float2 a = s45[j], b = s45[nxt];
                contS += 0.5f * (fabsf(a.x - b.x) + fabsf(a.y - b.y));
            } else {
                g_last_p45[rs] = s45[j];   // unique last valid in segment
            }
        }
    }
    if (tid == 0) {
        int f = SEG;
#pragma unroll
        for (int w2 = 0; w2 < 8; w2++) f = min(f, sfv[w2]);
        g_first_idx[rs] = f;
        if (f < SEG) g_first_p45[rs] = s45[f];
    }

    // ---- 5) block reduce + global atomic accumulate ----
    float vals[6] = {coordS, widthS, bceS, nvS, contS, reconS};
#pragma unroll
    for (int q = 0; q < 6; q++) {
        float v = warpReduceSumF(vals[q]);
        if (lane == 0) swred[q][wid] = v;
    }
    __syncthreads();
    if (wid == 0 && lane < 6) {
        float v = 0.f;
#pragma unroll
        for (int j = 0; j < 8; j++) v += swred[lane][j];
        atomicAdd(&g_acc[lane], v);
    }
    __syncthreads();

    // ---- 6) last-block finalize ----
    if (tid == 0) {
        __threadfence();   // release: publishes this block's writes (cumulative)
        unsigned int t = atomicAdd(&g_ticket, 1u);
        s_is_last = (t == (unsigned int)(nblocks - 1));
    }
    __syncthreads();
    if (!s_is_last) return;
    __threadfence();       // acquire (single block)

    // cross-segment continuity fixup: one row per thread, prefetched loads
    float fix = 0.f;
    for (int r = tid; r < B; r += TPB) {
        int    fidx[SEGS];
        float2 fp[SEGS], lp[SEGS];
#pragma unroll
        for (int s = 0; s < SEGS; s++) {
            int q = r * SEGS + s;
            fidx[s] = g_first_idx[q];
            fp[s]   = g_first_p45[q];
            lp[s]   = g_last_p45[q];
        }
        float2 nf = make_float2(0.f, 0.f);
        bool have = false;
#pragma unroll
        for (int s = SEGS - 1; s >= 0; s--) {
            if (fidx[s] < SEG) {
                if (have) fix += 0.5f * (fabsf(lp[s].x - nf.x) + fabsf(lp[s].y - nf.y));
                nf = fp[s];
                have = true;
            }
        }
    }
    {
        float v = warpReduceSumF(fix);
        if (lane == 0) swred[0][wid] = v;
    }
    __syncthreads();
    if (tid == 0) {
        float fsum = 0.f;
#pragma unroll
        for (int j = 0; j < 8; j++) fsum += swred[0][j];

        double t0 = (double)g_acc[0], t1 = (double)g_acc[1], t2 = (double)g_acc[2];
        double nv = (double)g_acc[3];
        double t4 = (double)g_acc[4] + (double)fsum;
        double t5 = (double)g_acc[5];

        double coord    = (nv > 0.0) ? t0 / fmax(nv * 6.0, 1.0) : 0.0;
        double width    = (nv > 0.0) ? t1 / fmax(nv * 2.0, 1.0) : 0.0;
        double validity = t2 / ((double)B * (double)M_ROW);
        double cont     = t4 / (double)B;
        double recon    = t5 / (double)nrec;
        out[0] = (float)(coord + width + 2.0 * validity + 0.2 * cont + 0.1 * recon);

        g_ticket = 0u;
#pragma unroll
        for (int q = 0; q < 6; q++) g_acc[q] = 0.f;
        __threadfence();
    }
}

extern "C" void kernel_launch(void* const* d_in, const int* in_sizes, int n_in,
                              void* d_out, int out_size)
{
    const float* preds = (const float*)d_in[0];
    const float* tgts  = (const float*)d_in[1];
    const float* rec   = (const float*)d_in[2];
    const float* img   = (const float*)d_in[3];

    const int B    = in_sizes[0] / (M_ROW * 9);
    const int nrec = in_sizes[2];
    const int nblocks = B * SEGS;   // 2048 — uniform grid, recon folded in

    loss_fused_kernel<<<nblocks, TPB>>>(preds, tgts, rec, img,
                                        (float*)d_out, B, nrec, nblocks);
}

// round 9
// speedup vs baseline: 1.3608x; 1.0743x over previous
#include <cuda_runtime.h>
#include <cstdint>

// ImprovedVectorizationLoss: fused masked-L1 + BCE + continuity + recon-MSE.
// R8 structure (2048 uniform blocks, 512 records each, recon folded under the
// cp.async staging) with smem cut to exactly 36KB by reusing the dead sp/st
// tile buffers for continuity/reduction scratch -> 6 blocks/SM.

#define M_ROW 4096
#define TPB   256
#define SEGS  8
#define SEG   (M_ROW / SEGS)         // 512
#define TILE  256
#define NTILE (SEG / TILE)           // 2
#define NF4T  (TILE * 9 / 4)         // 576 float4 per tile per tensor
#define BMAX  512
#define EPSV  1e-7f

__device__ float        g_acc[6];                  // [coord,width,bce,nvalid,cont,recon]
__device__ unsigned int g_ticket;
__device__ int          g_first_idx[BMAX * SEGS];
__device__ float2       g_first_p45[BMAX * SEGS];
__device__ float2       g_last_p45[BMAX * SEGS];

__device__ __forceinline__ float warpReduceSumF(float v) {
#pragma unroll
    for (int o = 16; o > 0; o >>= 1) v += __shfl_down_sync(0xffffffffu, v, o);
    return v;
}

__device__ __forceinline__ void cp16(void* s, const void* g) {
    unsigned saddr = (unsigned)__cvta_generic_to_shared(s);
    asm volatile("cp.async.cg.shared.global [%0], [%1], 16;" :: "r"(saddr), "l"(g));
}
#define CP_COMMIT() asm volatile("cp.async.commit_group;")
#define CP_WAIT(n)  asm volatile("cp.async.wait_group %0;" :: "n"(n))

__global__ __launch_bounds__(TPB, 6) void loss_fused_kernel(
    const float* __restrict__ preds, const float* __restrict__ tgts,
    const float* __restrict__ rec,   const float* __restrict__ img,
    float* __restrict__ out, int B, int nrec, int nblocks)
{
    __shared__ float sp[NTILE * TILE * 9];   // 18 KB (later aliased: s45 float2[512])
    __shared__ float st[NTILE * TILE * 9];   // 18 KB (later aliased: mask/red/flag)

    const int tid  = threadIdx.x;
    const int bid  = blockIdx.x;
    const int lane = tid & 31;
    const int wid  = tid >> 5;

    float coordS = 0.f, widthS = 0.f, bceS = 0.f, nvS = 0.f, contS = 0.f, reconS = 0.f;

    const size_t segbase = (size_t)bid * SEG * 9;
    const float4* p4 = reinterpret_cast<const float4*>(preds + segbase);
    const float4* t4 = reinterpret_cast<const float4*>(tgts  + segbase);

    // ---- 1) stage tile0 then tile1 via cp.async, separate commit groups ----
#pragma unroll
    for (int tl = 0; tl < NTILE; tl++) {
        float4* spd = reinterpret_cast<float4*>(sp) + tl * NF4T;
        float4* std_ = reinterpret_cast<float4*>(st) + tl * NF4T;
        for (int i = tid; i < NF4T; i += TPB) {
            cp16(&spd[i], &p4[tl * NF4T + i]);
            cp16(&std_[i], &t4[tl * NF4T + i]);
        }
        CP_COMMIT();
    }

    // ---- 2) recon MSE slice overlaps the cp.async fill ----
    {
        const float4* r4 = reinterpret_cast<const float4*>(rec);
        const float4* i4 = reinterpret_cast<const float4*>(img);
        const int n4 = nrec >> 2;
        for (int i = bid * TPB + tid; i < n4; i += nblocks * TPB) {
            float4 r = r4[i], m = i4[i];
            float dx = r.x - m.x, dy = r.y - m.y, dz = r.z - m.z, dw = r.w - m.w;
            reconS += dx * dx + dy * dy + dz * dz + dw * dw;
        }
    }

    // ---- 3) record losses; thread owns records tid (tile0) and 256+tid ----
    unsigned v0 = 0u, v1 = 0u;
    float2   q45[2];
#pragma unroll
    for (int tile = 0; tile < NTILE; tile++) {
        if (tile == 0) CP_WAIT(1); else CP_WAIT(0);
        __syncthreads();

        const float* pr = sp + (tile * TILE + tid) * 9;
        const float* tr = st + (tile * TILE + tid) * 9;
        float t8   = tr[8];
        float mask = (t8 > 0.5f) ? 1.0f : 0.0f;
        if (tile == 0) v0 = (t8 > 0.5f) ? 1u : 0u;
        else           v1 = (t8 > 0.5f) ? 1u : 0u;

        float a4 = pr[4], a5 = pr[5];
        coordS += (fabsf(pr[0] - tr[0]) + fabsf(pr[1] - tr[1]) + fabsf(pr[2] - tr[2])
                 + fabsf(pr[3] - tr[3]) + fabsf(a4 - tr[4]) + fabsf(a5 - tr[5])) * mask;
        widthS += (fabsf(pr[6] - tr[6]) + fabsf(pr[7] - tr[7])) * mask;

        float p = fminf(fmaxf(pr[8], EPSV), 1.0f - EPSV);
        bceS   += -(t8 * __logf(p) + (1.0f - t8) * __logf(1.0f - p));
        nvS    += mask;

        q45[tile] = make_float2(a4, a5);
    }
    __syncthreads();   // all sp/st reads done -> buffers reusable as scratch

    // ---- scratch aliases over the dead tile buffers ----
    float2*   s45f  = reinterpret_cast<float2*>(sp);        // 512 x float2
    unsigned* smask = reinterpret_cast<unsigned*>(st);      // words 0..15
    float*    swred = reinterpret_cast<float*>(st) + 32;    // 6 x 8 floats
    int*      slast = reinterpret_cast<int*>(st) + 96;      // 1 int

    s45f[tid]        = q45[0];
    s45f[TILE + tid] = q45[1];
    {
        unsigned b0 = __ballot_sync(0xffffffffu, v0 != 0u);
        unsigned b1 = __ballot_sync(0xffffffffu, v1 != 0u);
        if (lane == 0) { smask[wid] = b0; smask[8 + wid] = b1; }
    }
    __syncthreads();

    // ---- 4) continuity: next-valid via 16-word mask scan ----
    const int rs = bid;
#pragma unroll
    for (int t = 0; t < 2; t++) {
        unsigned vv = t ? v1 : v0;
        if (vv) {
            const int j = t * TILE + tid;
            const int k = j >> 5;                // == t*8 + wid
            unsigned rem = (lane < 31) ? (smask[k] & (0xFFFFFFFEu << lane)) : 0u;
            int k2 = k;
            while (rem == 0u && ++k2 < 16) rem = smask[k2];
            float2 a = q45[t];
            if (rem != 0u) {
                int nxt = (k2 << 5) + __ffs(rem) - 1;
                float2 nb = s45f[nxt];
                contS += 0.5f * (fabsf(a.x - nb.x) + fabsf(a.y - nb.y));
            } else {
                g_last_p45[rs] = a;              // unique last valid in segment
            }
        }
    }
    if (tid == 0) {
        int f = SEG;
#pragma unroll
        for (int k = 15; k >= 0; k--)
            if (smask[k]) f = (k << 5) + __ffs(smask[k]) - 1;
        g_first_idx[rs] = f;
        if (f < SEG) g_first_p45[rs] = s45f[f];
    }

    // ---- 5) block reduce + global atomic accumulate ----
    float vals[6] = {coordS, widthS, bceS, nvS, contS, reconS};
#pragma unroll
    for (int q = 0; q < 6; q++) {
        float v = warpReduceSumF(vals[q]);
        if (lane == 0) swred[q * 8 + wid] = v;
    }
    __syncthreads();
    if (wid == 0 && lane < 6) {
        float v = 0.f;
#pragma unroll
        for (int j = 0; j < 8; j++) v += swred[lane * 8 + j];
        atomicAdd(&g_acc[lane], v);
    }
    __syncthreads();

    // ---- 6) last-block finalize ----
    if (tid == 0) {
        __threadfence();   // release: publishes this block's writes (cumulative)
        unsigned int t = atomicAdd(&g_ticket, 1u);
        slast[0] = (t == (unsigned int)(nblocks - 1)) ? 1 : 0;
    }
    __syncthreads();
    if (!slast[0]) return;
    __threadfence();       // acquire (single block)

    // cross-segment continuity fixup: one row per thread, prefetched loads
    float fix = 0.f;
    for (int r = tid; r < B; r += TPB) {
        int    fidx[SEGS];
        float2 fp[SEGS], lp[SEGS];
#pragma unroll
        for (int s = 0; s < SEGS; s++) {
            int q = r * SEGS + s;
            fidx[s] = g_first_idx[q];
            fp[s]   = g_first_p45[q];
            lp[s]   = g_last_p45[q];
        }
        float2 nf = make_float2(0.f, 0.f);
        bool have = false;
#pragma unroll
        for (int s = SEGS - 1; s >= 0; s--) {
            if (fidx[s] < SEG) {
                if (have) fix += 0.5f * (fabsf(lp[s].x - nf.x) + fabsf(lp[s].y - nf.y));
                nf = fp[s];
                have = true;
            }
        }
    }
    {
        float v = warpReduceSumF(fix);
        if (lane == 0) swred[wid] = v;
    }
    __syncthreads();
    if (tid == 0) {
        float fsum = 0.f;
#pragma unroll
        for (int j = 0; j < 8; j++) fsum += swred[j];

        double t0 = (double)g_acc[0], t1 = (double)g_acc[1], t2 = (double)g_acc[2];
        double nv = (double)g_acc[3];
        double t4 = (double)g_acc[4] + (double)fsum;
        double t5 = (double)g_acc[5];

        double coord    = (nv > 0.0) ? t0 / fmax(nv * 6.0, 1.0) : 0.0;
        double width    = (nv > 0.0) ? t1 / fmax(nv * 2.0, 1.0) : 0.0;
        double validity = t2 / ((double)B * (double)M_ROW);
        double cont     = t4 / (double)B;
        double recon    = t5 / (double)nrec;
        out[0] = (float)(coord + width + 2.0 * validity + 0.2 * cont + 0.1 * recon);

        g_ticket = 0u;
#pragma unroll
        for (int q = 0; q < 6; q++) g_acc[q] = 0.f;
        __threadfence();
    }
}

extern "C" void kernel_launch(void* const* d_in, const int* in_sizes, int n_in,
                              void* d_out, int out_size)
{
    const float* preds = (const float*)d_in[0];
    const float* tgts  = (const float*)d_in[1];
    const float* rec   = (const float*)d_in[2];
    const float* img   = (const float*)d_in[3];

    const int B    = in_sizes[0] / (M_ROW * 9);
    const int nrec = in_sizes[2];
    const int nblocks = B * SEGS;   // 2048 — uniform grid, recon folded in

    loss_fused_kernel<<<nblocks, TPB>>>(preds, tgts, rec, img,
                                        (float*)d_out, B, nrec, nblocks);
}

// round 10
// speedup vs baseline: 1.4738x; 1.0830x over previous
#include <cuda_runtime.h>
#include <cstdint>

// ImprovedVectorizationLoss: fused masked-L1 + BCE + continuity + recon-MSE.
// Persistent work-stealing kernel: 740 resident blocks (5/SM), segments of
// 512 records claimed via an atomic counter; each block prefetches its next
// segment (cp.async) while running continuity of the current one. Global
// atomics + last-block ticket finalize & self-reset (incl. work counter).

#define M_ROW 4096
#define TPB   256
#define SEGS  8
#define SEG   (M_ROW / SEGS)         // 512
#define TILE  256
#define NTILE (SEG / TILE)           // 2
#define NF4T  (TILE * 9 / 4)         // 576 float4 per tile per tensor
#define NBLOCKS 740                  // 5 blocks/SM x 148 SMs, single wave
#define BMAX  512
#define EPSV  1e-7f

__device__ float        g_acc[6];                  // [coord,width,bce,nvalid,cont,recon]
__device__ unsigned int g_ticket;
__device__ unsigned int g_work;                    // segment work counter
__device__ int          g_first_idx[BMAX * SEGS];
__device__ float2       g_first_p45[BMAX * SEGS];
__device__ float2       g_last_p45[BMAX * SEGS];

__device__ __forceinline__ float warpReduceSumF(float v) {
#pragma unroll
    for (int o = 16; o > 0; o >>= 1) v += __shfl_down_sync(0xffffffffu, v, o);
    return v;
}

__device__ __forceinline__ void cp16(void* s, const void* g) {
    unsigned saddr = (unsigned)__cvta_generic_to_shared(s);
    asm volatile("cp.async.cg.shared.global [%0], [%1], 16;" :: "r"(saddr), "l"(g));
}
#define CP_COMMIT() asm volatile("cp.async.commit_group;")
#define CP_WAIT(n)  asm volatile("cp.async.wait_group %0;" :: "n"(n))

__global__ __launch_bounds__(TPB, 5) void loss_fused_kernel(
    const float* __restrict__ preds, const float* __restrict__ tgts,
    const float* __restrict__ rec,   const float* __restrict__ img,
    float* __restrict__ out, int B, int nrec)
{
    __shared__ float    sp[NTILE * TILE * 9];   // 18 KB
    __shared__ float    st[NTILE * TILE * 9];   // 18 KB
    __shared__ float2   s45f[SEG];              // 4 KB (dedicated: sp refilled during continuity)
    __shared__ unsigned smask[16];
    __shared__ float    swred[6][8];
    __shared__ int      s_seg;                  // next stolen segment
    __shared__ int      slast;

    const int tid  = threadIdx.x;
    const int bid  = blockIdx.x;
    const int lane = tid & 31;
    const int wid  = tid >> 5;
    const int NSEG = B * SEGS;

    float coordS = 0.f, widthS = 0.f, bceS = 0.f, nvS = 0.f, contS = 0.f, reconS = 0.f;

    // ---- prologue: steal first segment, start its prefetch ----
    if (tid == 0) s_seg = (int)atomicAdd(&g_work, 1u);
    __syncthreads();
    int s0 = s_seg;

    if (s0 < NSEG) {
        const float4* p4 = reinterpret_cast<const float4*>(preds + (size_t)s0 * SEG * 9);
        const float4* t4 = reinterpret_cast<const float4*>(tgts  + (size_t)s0 * SEG * 9);
#pragma unroll
        for (int tl = 0; tl < NTILE; tl++) {
            float4* spd = reinterpret_cast<float4*>(sp) + tl * NF4T;
            float4* std_ = reinterpret_cast<float4*>(st) + tl * NF4T;
            for (int i = tid; i < NF4T; i += TPB) {
                cp16(&spd[i], &p4[tl * NF4T + i]);
                cp16(&std_[i], &t4[tl * NF4T + i]);
            }
            CP_COMMIT();
        }
    }

    // ---- recon MSE slice overlaps the first prefetch ----
    {
        const float4* r4 = reinterpret_cast<const float4*>(rec);
        const float4* i4 = reinterpret_cast<const float4*>(img);
        const int n4 = nrec >> 2;
        for (int i = bid * TPB + tid; i < n4; i += NBLOCKS * TPB) {
            float4 r = r4[i], m = i4[i];
            float dx = r.x - m.x, dy = r.y - m.y, dz = r.z - m.z, dw = r.w - m.w;
            reconS += dx * dx + dy * dy + dz * dz + dw * dw;
        }
    }

    // ---- persistent segment loop ----
    while (s0 < NSEG) {
        // steal the next segment early; latency hides under tile0 wait/compute
        if (tid == 0) s_seg = (int)atomicAdd(&g_work, 1u);

        unsigned v0 = 0u, v1 = 0u;
        float2   q45[2];
#pragma unroll
        for (int tile = 0; tile < NTILE; tile++) {
            if (tile == 0) CP_WAIT(1); else CP_WAIT(0);
            __syncthreads();   // tile data visible (also publishes s_seg)

            const float* pr = sp + (tile * TILE + tid) * 9;
            const float* tr = st + (tile * TILE + tid) * 9;
            float t8   = tr[8];
            float mask = (t8 > 0.5f) ? 1.0f : 0.0f;
            if (tile == 0) v0 = (t8 > 0.5f) ? 1u : 0u;
            else           v1 = (t8 > 0.5f) ? 1u : 0u;

            float a4 = pr[4], a5 = pr[5];
            coordS += (fabsf(pr[0] - tr[0]) + fabsf(pr[1] - tr[1]) + fabsf(pr[2] - tr[2])
                     + fabsf(pr[3] - tr[3]) + fabsf(a4 - tr[4]) + fabsf(a5 - tr[5])) * mask;
            widthS += (fabsf(pr[6] - tr[6]) + fabsf(pr[7] - tr[7])) * mask;

            float p = fminf(fmaxf(pr[8], EPSV), 1.0f - EPSV);
            bceS   += -(t8 * __logf(p) + (1.0f - t8) * __logf(1.0f - p));
            nvS    += mask;

            q45[tile] = make_float2(a4, a5);
            s45f[tile * TILE + tid] = q45[tile];
        }
        {
            unsigned b0 = __ballot_sync(0xffffffffu, v0 != 0u);
            unsigned b1 = __ballot_sync(0xffffffffu, v1 != 0u);
            if (lane == 0) { smask[wid] = b0; smask[8 + wid] = b1; }
        }
        __syncthreads();   // sp/st consumed; s45f + masks visible

        const int s1 = s_seg;

        // ---- prefetch next segment into the freed buffers ----
        if (s1 < NSEG) {
            const float4* p4 = reinterpret_cast<const float4*>(preds + (size_t)s1 * SEG * 9);
            const float4* t4 = reinterpret_cast<const float4*>(tgts  + (size_t)s1 * SEG * 9);
#pragma unroll
            for (int tl = 0; tl < NTILE; tl++) {
                float4* spd = reinterpret_cast<float4*>(sp) + tl * NF4T;
                float4* std_ = reinterpret_cast<float4*>(st) + tl * NF4T;
                for (int i = tid; i < NF4T; i += TPB) {
                    cp16(&spd[i], &p4[tl * NF4T + i]);
                    cp16(&std_[i], &t4[tl * NF4T + i]);
                }
                CP_COMMIT();
            }
        }

        // ---- continuity of s0 runs under the prefetch ----
        const int rs = s0;
#pragma unroll
        for (int t = 0; t < 2; t++) {
            unsigned vv = t ? v1 : v0;
            if (vv) {
                const int j = t * TILE + tid;
                const int k = j >> 5;
                unsigned rem = (lane < 31) ? (smask[k] & (0xFFFFFFFEu << lane)) : 0u;
                int k2 = k;
                while (rem == 0u && ++k2 < 16) rem = smask[k2];
                float2 a = q45[t];
                if (rem != 0u) {
                    int nxt = (k2 << 5) + __ffs(rem) - 1;
                    float2 nb = s45f[nxt];
                    contS += 0.5f * (fabsf(a.x - nb.x) + fabsf(a.y - nb.y));
                } else {
                    g_last_p45[rs] = a;          // unique last valid in segment
                }
            }
        }
        if (tid == 0) {
            int f = SEG;
#pragma unroll
            for (int k = 15; k >= 0; k--)
                if (smask[k]) f = (k << 5) + __ffs(smask[k]) - 1;
            g_first_idx[rs] = f;
            if (f < SEG) g_first_p45[rs] = s45f[f];
        }

        s0 = s1;
        // loop-top CP_WAIT+sync orders next compute after this continuity,
        // so s45f/smask reuse is safe.
    }

    // ---- block reduce + global atomic accumulate ----
    float vals[6] = {coordS, widthS, bceS, nvS, contS, reconS};
#pragma unroll
    for (int q = 0; q < 6; q++) {
        float v = warpReduceSumF(vals[q]);
        if (lane == 0) swred[q][wid] = v;
    }
    __syncthreads();
    if (wid == 0 && lane < 6) {
        float v = 0.f;
#pragma unroll
        for (int j = 0; j < 8; j++) v += swred[lane][j];
        atomicAdd(&g_acc[lane], v);
    }
    __syncthreads();

    // ---- last-block finalize ----
    if (tid == 0) {
        __threadfence();   // release: publishes this block's writes (cumulative)
        unsigned int t = atomicAdd(&g_ticket, 1u);
        slast = (t == (unsigned int)(NBLOCKS - 1)) ? 1 : 0;
    }
    __syncthreads();
    if (!slast) return;
    __threadfence();       // acquire (single block)

    // cross-segment continuity fixup: one row per thread, prefetched loads
    float fix = 0.f;
    for (int r = tid; r < B; r += TPB) {
        int    fidx[SEGS];
        float2 fp[SEGS], lp[SEGS];
#pragma unroll
        for (int s = 0; s < SEGS; s++) {
            int q = r * SEGS + s;
            fidx[s] = g_first_idx[q];
            fp[s]   = g_first_p45[q];
            lp[s]   = g_last_p45[q];
        }
        float2 nf = make_float2(0.f, 0.f);
        bool have = false;
#pragma unroll
        for (int s = SEGS - 1; s >= 0; s--) {
            if (fidx[s] < SEG) {
                if (have) fix += 0.5f * (fabsf(lp[s].x - nf.x) + fabsf(lp[s].y - nf.y));
                nf = fp[s];
                have = true;
            }
        }
    }
    {
        float v = warpReduceSumF(fix);
        if (lane == 0) swred[0][wid] = v;
    }
    __syncthreads();
    if (tid == 0) {
        float fsum = 0.f;
#pragma unroll
        for (int j = 0; j < 8; j++) fsum += swred[0][j];

        double t0 = (double)g_acc[0], t1 = (double)g_acc[1], t2 = (double)g_acc[2];
        double nv = (double)g_acc[3];
        double t4 = (double)g_acc[4] + (double)fsum;
        double t5 = (double)g_acc[5];

        double coord    = (nv > 0.0) ? t0 / fmax(nv * 6.0, 1.0) : 0.0;
        double width    = (nv > 0.0) ? t1 / fmax(nv * 2.0, 1.0) : 0.0;
        double validity = t2 / ((double)B * (double)M_ROW);
        double cont     = t4 / (double)B;
        double recon    = t5 / (double)nrec;
        out[0] = (float)(coord + width + 2.0 * validity + 0.2 * cont + 0.1 * recon);

        // self-reset for the next graph replay
        g_ticket = 0u;
        g_work   = 0u;
#pragma unroll
        for (int q = 0; q < 6; q++) g_acc[q] = 0.f;
        __threadfence();
    }
}

extern "C" void kernel_launch(void* const* d_in, const int* in_sizes, int n_in,
                              void* d_out, int out_size)
{
    const float* preds = (const float*)d_in[0];
    const float* tgts  = (const float*)d_in[1];
    const float* rec   = (const float*)d_in[2];
    const float* img   = (const float*)d_in[3];

    const int B    = in_sizes[0] / (M_ROW * 9);
    const int nrec = in_sizes[2];

    loss_fused_kernel<<<NBLOCKS, TPB>>>(preds, tgts, rec, img,
                                        (float*)d_out, B, nrec);
}